// round 3
// baseline (speedup 1.0000x reference)
#include <cuda_runtime.h>

typedef unsigned long long ull;

#define TLEN 4000
#define HID  64
#define BT   2
#define NTHR 384
#define NW   (TLEN + 2)

__device__ __forceinline__ void ffma2(ull &d, ull a, ull b) {
    asm("fma.rn.f32x2 %0, %1, %2, %0;" : "+l"(d) : "l"(a), "l"(b));
}
__device__ __forceinline__ float2 unpack2(ull v) {
    float2 r;
    asm("mov.b64 {%0, %1}, %2;" : "=f"(r.x), "=f"(r.y) : "l"(v));
    return r;
}
__device__ __forceinline__ ull pack2(float x, float y) {
    ull r;
    asm("mov.b64 %0, {%1, %2};" : "=l"(r) : "f"(x), "f"(y));
    return r;
}
__device__ __forceinline__ float fsigmoid(float v) {
    return __fdividef(1.0f, 1.0f + __expf(-v));
}
__device__ __forceinline__ float ftanh(float v) {
    float e = __expf(2.0f * v);
    return 1.0f - __fdividef(2.0f, e + 1.0f);
}

__global__ void __launch_bounds__(NTHR, 1)
lstm2_ws(const float* __restrict__ x,
         const float* __restrict__ W_ih0,
         const float* __restrict__ W_hh0,
         const float* __restrict__ b_ih0,
         const float* __restrict__ b_hh0,
         const float* __restrict__ W_ih1,
         const float* __restrict__ W_hh1,
         const float* __restrict__ b_ih1,
         const float* __restrict__ b_hh1,
         const float* __restrict__ W_fc,
         const float* __restrict__ b_fc,
         float* __restrict__ out)
{
    __shared__ __align__(16) float sh_x[BT * TLEN];        // 32 KB
    __shared__ __align__(16) float sh_h0[2][BT][HID];      // double-buffered h0
    __shared__ __align__(16) float sh_h1[2][BT][HID];      // double-buffered h1
    __shared__ __align__(16) float sh_gA[256][BT];         // layer0 gates
    __shared__ __align__(16) float sh_gB[2][256][BT];      // layer1 gates, dbl-buf

    const int tid   = threadIdx.x;
    const int bbase = blockIdx.x * BT;

    // Stage x (contiguous 2 batch rows)
    {
        const float4* xg = (const float4*)(x + (size_t)bbase * TLEN);
        float4* xs = (float4*)sh_x;
        for (int i = tid; i < BT * TLEN / 4; i += NTHR) xs[i] = xg[i];
    }
    if (tid < 2 * BT * HID) {                 // 256 floats each
        ((float*)sh_h0)[tid] = 0.0f;
        ((float*)sh_h1)[tid] = 0.0f;
    }

    if (tid < 256) {
        // ================= GROUP B: layer-1 matvec (warps 0-7) =================
        const int r = tid;                    // layer1 gate row
        ull wb[64];                           // [W_ih1 row | W_hh1 row]
        {
            const ulonglong2* p = (const ulonglong2*)(W_ih1 + r * HID);
            #pragma unroll
            for (int q = 0; q < 16; q++) { ulonglong2 v = p[q]; wb[2*q] = v.x; wb[2*q+1] = v.y; }
            p = (const ulonglong2*)(W_hh1 + r * HID);
            #pragma unroll
            for (int q = 0; q < 16; q++) { ulonglong2 v = p[q]; wb[32+2*q] = v.x; wb[33+2*q] = v.y; }
        }
        const float bB = b_ih1[r] + b_hh1[r];
        __syncthreads();                                        // R(0)

        for (int w = 0; w < NW; ++w) {
            const bool act = (w >= 1) && (w <= TLEN);           // step k = w-1
            ull a0x = pack2(bB, 0.0f), a0y = pack2(0.0f, 0.0f);
            ull a1x = a0x,             a1y = a0y;
            if (act) {  // h0 half: W_ih1 · h0(w-1)
                const ulonglong2* h0b0 = (const ulonglong2*)&sh_h0[(w-1)&1][0][0];
                const ulonglong2* h0b1 = (const ulonglong2*)&sh_h0[(w-1)&1][1][0];
                #pragma unroll
                for (int q = 0; q < 16; q++) {
                    ulonglong2 v0 = h0b0[q], v1 = h0b1[q];
                    ffma2(a0x, wb[2*q],   v0.x);
                    ffma2(a1x, wb[2*q],   v1.x);
                    ffma2(a0y, wb[2*q+1], v0.y);
                    ffma2(a1y, wb[2*q+1], v1.y);
                }
            }
            asm volatile("bar.sync 3, 384;" ::: "memory");      // h1(w-2) ready
            if (act) {  // h1 half: W_hh1 · h1(w-2)
                const ulonglong2* h1b0 = (const ulonglong2*)&sh_h1[w&1][0][0];
                const ulonglong2* h1b1 = (const ulonglong2*)&sh_h1[w&1][1][0];
                #pragma unroll
                for (int q = 0; q < 16; q++) {
                    ulonglong2 v0 = h1b0[q], v1 = h1b1[q];
                    ffma2(a0x, wb[32+2*q], v0.x);
                    ffma2(a1x, wb[32+2*q], v1.x);
                    ffma2(a0y, wb[33+2*q], v0.y);
                    ffma2(a1y, wb[33+2*q], v1.y);
                }
                float2 s0 = unpack2(a0x), t0 = unpack2(a0y);
                float2 s1 = unpack2(a1x), t1 = unpack2(a1y);
                ((float2*)sh_gB[(w-1)&1])[r] =
                    make_float2((s0.x + s0.y) + (t0.x + t0.y),
                                (s1.x + s1.y) + (t1.x + t1.y));
            }
            __syncthreads();                                    // R(w+1)
        }
    } else {
        // ====== GROUP A: layer-0 matvec + both pointwise stages (warps 8-11) ======
        const int a  = tid - 256;             // 0..127
        const int r0 = 2 * a, r1 = 2 * a + 1; // two layer0 gate rows
        ull w0[32], w1[32];
        {
            const ulonglong2* p = (const ulonglong2*)(W_hh0 + r0 * HID);
            #pragma unroll
            for (int q = 0; q < 16; q++) { ulonglong2 v = p[q]; w0[2*q] = v.x; w0[2*q+1] = v.y; }
            p = (const ulonglong2*)(W_hh0 + r1 * HID);
            #pragma unroll
            for (int q = 0; q < 16; q++) { ulonglong2 v = p[q]; w1[2*q] = v.x; w1[2*q+1] = v.y; }
        }
        const float wx0 = W_ih0[r0], wx1 = W_ih0[r1];
        const float bA0 = b_ih0[r0] + b_hh0[r0];
        const float bA1 = b_ih0[r1] + b_hh0[r1];
        const int pb = a >> 6, pj = a & (HID - 1);  // pointwise item (batch, unit)
        float c0 = 0.0f, c1 = 0.0f;
        __syncthreads();                                        // R(0)

        for (int w = 0; w < NW; ++w) {
            // ---- pw1(w-2): layer1 pointwise, produces h1(w-2) ----
            if (w >= 2) {
                const float (*gB)[BT] = sh_gB[w & 1];           // slot (w-2)&1
                float gi = gB[pj      ][pb];
                float gf = gB[pj +  64][pb];
                float gc = gB[pj + 128][pb];
                float go = gB[pj + 192][pb];
                float iv = fsigmoid(gi), fv = fsigmoid(gf), ov = fsigmoid(go);
                float cv = ftanh(gc);
                c1 = fv * c1 + iv * cv;
                sh_h1[w & 1][pb][pj] = ov * ftanh(c1);
            }
            asm volatile("bar.arrive 3, 384;" ::: "memory");    // h1 ready -> B
            // ---- gA(w): layer0 matvec, uses h0(w-1) ----
            if (w < TLEN) {
                const float xa = sh_x[w];
                const float xb = sh_x[TLEN + w];
                ull a00 = pack2(fmaf(xa, wx0, bA0), 0.0f);
                ull a01 = pack2(fmaf(xb, wx0, bA0), 0.0f);
                ull a10 = pack2(fmaf(xa, wx1, bA1), 0.0f);
                ull a11 = pack2(fmaf(xb, wx1, bA1), 0.0f);
                const ulonglong2* h0b0 = (const ulonglong2*)&sh_h0[(w+1)&1][0][0];
                const ulonglong2* h0b1 = (const ulonglong2*)&sh_h0[(w+1)&1][1][0];
                #pragma unroll
                for (int q = 0; q < 16; q++) {
                    ulonglong2 v0 = h0b0[q], v1 = h0b1[q];
                    ffma2(a00, w0[2*q],   v0.x);
                    ffma2(a01, w0[2*q],   v1.x);
                    ffma2(a10, w1[2*q],   v0.x);
                    ffma2(a11, w1[2*q],   v1.x);
                    ffma2(a00, w0[2*q+1], v0.y);
                    ffma2(a01, w0[2*q+1], v1.y);
                    ffma2(a10, w1[2*q+1], v0.y);
                    ffma2(a11, w1[2*q+1], v1.y);
                }
                float2 p0 = unpack2(a00), p1 = unpack2(a01);
                float2 p2 = unpack2(a10), p3 = unpack2(a11);
                ((float2*)sh_gA)[r0] = make_float2(p0.x + p0.y, p1.x + p1.y);
                ((float2*)sh_gA)[r1] = make_float2(p2.x + p2.y, p3.x + p3.y);
            }
            asm volatile("bar.sync 1, 128;" ::: "memory");      // A-internal
            // ---- pw0(w): layer0 pointwise, produces h0(w) ----
            if (w < TLEN) {
                float gi = sh_gA[pj      ][pb];
                float gf = sh_gA[pj +  64][pb];
                float gc = sh_gA[pj + 128][pb];
                float go = sh_gA[pj + 192][pb];
                float iv = fsigmoid(gi), fv = fsigmoid(gf), ov = fsigmoid(go);
                float cv = ftanh(gc);
                c0 = fv * c0 + iv * cv;
                sh_h0[w & 1][pb][pj] = ov * ftanh(c0);
            }
            __syncthreads();                                    // R(w+1)
        }
    }

    // ---- FC head on final h1 (step 3999 -> slot 3999&1 = 1) ----
    if (tid < 256) {
        const int e  = tid & 127;
        const int bb = tid >> 7;
        float acc = b_fc[e];
        const float* wr = W_fc + e * HID;
        const float* hv = &sh_h1[1][bb][0];
        #pragma unroll
        for (int j = 0; j < HID; j += 4) {
            acc = fmaf(wr[j],     hv[j],     acc);
            acc = fmaf(wr[j + 1], hv[j + 1], acc);
            acc = fmaf(wr[j + 2], hv[j + 2], acc);
            acc = fmaf(wr[j + 3], hv[j + 3], acc);
        }
        out[(size_t)(bbase + bb) * 128 + e] = acc;
    }
}

extern "C" void kernel_launch(void* const* d_in, const int* in_sizes, int n_in,
                              void* d_out, int out_size) {
    (void)in_sizes; (void)n_in; (void)out_size;
    lstm2_ws<<<128, NTHR>>>(
        (const float*)d_in[0],   // x
        (const float*)d_in[1],   // W_ih0
        (const float*)d_in[2],   // W_hh0
        (const float*)d_in[3],   // b_ih0
        (const float*)d_in[4],   // b_hh0
        (const float*)d_in[5],   // W_ih1
        (const float*)d_in[6],   // W_hh1
        (const float*)d_in[7],   // b_ih1
        (const float*)d_in[8],   // b_hh1
        (const float*)d_in[9],   // W_fc
        (const float*)d_in[10],  // b_fc
        (float*)d_out);
}

// round 4
// speedup vs baseline: 1.3149x; 1.3149x over previous
#include <cuda_runtime.h>

typedef unsigned long long ull;

#define TLEN 4000
#define HID  64
#define BT   2
#define NTHR 256

__device__ __forceinline__ void ffma2(ull &d, ull a, ull b) {
    asm("fma.rn.f32x2 %0, %1, %2, %0;" : "+l"(d) : "l"(a), "l"(b));
}
__device__ __forceinline__ float2 unpack2(ull v) {
    float2 r;
    asm("mov.b64 {%0, %1}, %2;" : "=f"(r.x), "=f"(r.y) : "l"(v));
    return r;
}
__device__ __forceinline__ ull pack2(float x, float y) {
    ull r;
    asm("mov.b64 %0, {%1, %2};" : "=l"(r) : "f"(x), "f"(y));
    return r;
}
__device__ __forceinline__ float tanha(float x) {
    float r;
    asm("tanh.approx.f32 %0, %1;" : "=f"(r) : "f"(x));
    return r;
}
__device__ __forceinline__ float fsigmoid(float x) {
    // sigmoid(x) = 0.5*tanh(0.5x) + 0.5  (1 MUFU + FMA)
    return fmaf(tanha(0.5f * x), 0.5f, 0.5f);
}

__global__ void __launch_bounds__(NTHR, 1)
lstm2_wl(const float* __restrict__ x,
         const float* __restrict__ W_ih0,
         const float* __restrict__ W_hh0,
         const float* __restrict__ b_ih0,
         const float* __restrict__ b_hh0,
         const float* __restrict__ W_ih1,
         const float* __restrict__ W_hh1,
         const float* __restrict__ b_ih1,
         const float* __restrict__ b_hh1,
         const float* __restrict__ W_fc,
         const float* __restrict__ b_fc,
         float* __restrict__ out)
{
    __shared__ __align__(16) float sh_x[BT * TLEN];       // 32 KB staged input
    __shared__ __align__(16) float sh_h[2][BT][2 * HID];  // dbl-buffered [h0|h1]
    __shared__ __align__(16) float sh_s[8][32][4];        // warp-local gate xchg

    const int tid   = threadIdx.x;
    const int w     = tid >> 5;
    const int l     = tid & 31;
    const int j     = l & 7;          // unit-local
    const int q     = l >> 3;         // gate index (i,f,g,o) AND pointwise combo
    const int u     = 8 * w + j;      // unit 0..63
    const int row   = q * HID + u;    // gate row this thread owns
    const int bbase = blockIdx.x * BT;

    // Stage x (two contiguous batch rows)
    {
        const float4* xg = (const float4*)(x + (size_t)bbase * TLEN);
        float4* xs = (float4*)sh_x;
        for (int i = tid; i < BT * TLEN / 4; i += NTHR) xs[i] = xg[i];
    }
    ((float2*)sh_h)[tid] = make_float2(0.0f, 0.0f);   // zero both slots (512 f)

    // Per-thread weight rows in registers (packed f32 pairs).
    ull wA[32], wI[32], wH[32];   // W_hh0 / W_ih1 / W_hh1 row `row`
    {
        const ulonglong2* p = (const ulonglong2*)(W_hh0 + row * HID);
        #pragma unroll
        for (int t = 0; t < 16; t++) { ulonglong2 v = p[t]; wA[2*t] = v.x; wA[2*t+1] = v.y; }
        p = (const ulonglong2*)(W_ih1 + row * HID);
        #pragma unroll
        for (int t = 0; t < 16; t++) { ulonglong2 v = p[t]; wI[2*t] = v.x; wI[2*t+1] = v.y; }
        p = (const ulonglong2*)(W_hh1 + row * HID);
        #pragma unroll
        for (int t = 0; t < 16; t++) { ulonglong2 v = p[t]; wH[2*t] = v.x; wH[2*t+1] = v.y; }
    }
    const float wx    = W_ih0[row];
    const float biasA = b_ih0[row] + b_hh0[row];
    const float biasB = b_ih1[row] + b_hh1[row];

    // Pointwise combo for this lane: q -> (layer Lq, batch bq), unit u.
    const int Lq = q >> 1;
    const int bq = q & 1;
    const int hoff = Lq * HID + u;
    float c = 0.0f;

    __syncthreads();

    // Iter k: matvec gA(k) [layer0 step k] + gB(k-1) [layer1 step k-1],
    // warp-local pointwise -> h0(k), h1(k-1). ONE CTA barrier per step.
    for (int k = 0; k <= TLEN; ++k) {
        const int rs = (k + 1) & 1;   // read slot  (= writes of iter k-1)
        const int ws = k & 1;         // write slot
        // ---- fused matvec ----
        {
            const int xk = (k < TLEN) ? k : TLEN - 1;
            const float xa = sh_x[xk];
            const float xb = sh_x[TLEN + xk];
            ull aA0x = pack2(fmaf(xa, wx, biasA), 0.0f), aA0y = pack2(0.0f, 0.0f);
            ull aA1x = pack2(fmaf(xb, wx, biasA), 0.0f), aA1y = pack2(0.0f, 0.0f);
            ull aB0x = pack2(biasB, 0.0f),               aB0y = pack2(0.0f, 0.0f);
            ull aB1x = aB0x,                             aB1y = pack2(0.0f, 0.0f);

            const ulonglong2* h0b0 = (const ulonglong2*)&sh_h[rs][0][0];
            const ulonglong2* h0b1 = (const ulonglong2*)&sh_h[rs][1][0];
            const ulonglong2* h1b0 = (const ulonglong2*)&sh_h[rs][0][HID];
            const ulonglong2* h1b1 = (const ulonglong2*)&sh_h[rs][1][HID];

            #pragma unroll
            for (int t = 0; t < 16; t++) {        // h0 feeds wA and wI
                ulonglong2 v0 = h0b0[t], v1 = h0b1[t];
                ffma2(aA0x, wA[2*t],   v0.x);
                ffma2(aA1x, wA[2*t],   v1.x);
                ffma2(aB0x, wI[2*t],   v0.x);
                ffma2(aB1x, wI[2*t],   v1.x);
                ffma2(aA0y, wA[2*t+1], v0.y);
                ffma2(aA1y, wA[2*t+1], v1.y);
                ffma2(aB0y, wI[2*t+1], v0.y);
                ffma2(aB1y, wI[2*t+1], v1.y);
            }
            #pragma unroll
            for (int t = 0; t < 16; t++) {        // h1 feeds wH
                ulonglong2 v0 = h1b0[t], v1 = h1b1[t];
                ffma2(aB0x, wH[2*t],   v0.x);
                ffma2(aB1x, wH[2*t],   v1.x);
                ffma2(aB0y, wH[2*t+1], v0.y);
                ffma2(aB1y, wH[2*t+1], v1.y);
            }
            float2 r0 = unpack2(aA0x), r1 = unpack2(aA0y);
            float2 r2 = unpack2(aA1x), r3 = unpack2(aA1y);
            float2 s0 = unpack2(aB0x), s1 = unpack2(aB0y);
            float2 s2 = unpack2(aB1x), s3 = unpack2(aB1y);
            float4 gv = make_float4((r0.x + r0.y) + (r1.x + r1.y),
                                    (r2.x + r2.y) + (r3.x + r3.y),
                                    (s0.x + s0.y) + (s1.x + s1.y),
                                    (s2.x + s2.y) + (s3.x + s3.y));
            *(float4*)&sh_s[w][l][0] = gv;        // {gA_b0, gA_b1, gB_b0, gB_b1}
        }
        __syncwarp();
        // ---- warp-local pointwise: lane -> (combo q, unit u) ----
        {
            const bool active = (q < 2) ? (k < TLEN) : (k >= 1);
            float g_i = sh_s[w][j     ][q];
            float g_f = sh_s[w][j +  8][q];
            float g_c = sh_s[w][j + 16][q];
            float g_o = sh_s[w][j + 24][q];
            float iv = fsigmoid(g_i), fv = fsigmoid(g_f), ov = fsigmoid(g_o);
            float cv = tanha(g_c);
            float cn = fmaf(fv, c, iv * cv);
            if (active) {
                c = cn;
                sh_h[ws][bq][hoff] = ov * tanha(c);
            }
        }
        __syncthreads();
    }

    // ---- FC head on final h1 (written at k=4000 -> slot 0) ----
    {
        const int e  = tid & 127;
        const int bb = tid >> 7;
        float acc = b_fc[e];
        const float* wr = W_fc + e * HID;
        const float* hv = &sh_h[0][bb][HID];
        #pragma unroll
        for (int t = 0; t < HID; t += 4) {
            acc = fmaf(wr[t],     hv[t],     acc);
            acc = fmaf(wr[t + 1], hv[t + 1], acc);
            acc = fmaf(wr[t + 2], hv[t + 2], acc);
            acc = fmaf(wr[t + 3], hv[t + 3], acc);
        }
        out[(size_t)(bbase + bb) * 128 + e] = acc;
    }
}

extern "C" void kernel_launch(void* const* d_in, const int* in_sizes, int n_in,
                              void* d_out, int out_size) {
    (void)in_sizes; (void)n_in; (void)out_size;
    lstm2_wl<<<128, NTHR>>>(
        (const float*)d_in[0],   // x
        (const float*)d_in[1],   // W_ih0
        (const float*)d_in[2],   // W_hh0
        (const float*)d_in[3],   // b_ih0
        (const float*)d_in[4],   // b_hh0
        (const float*)d_in[5],   // W_ih1
        (const float*)d_in[6],   // W_hh1
        (const float*)d_in[7],   // b_ih1
        (const float*)d_in[8],   // b_hh1
        (const float*)d_in[9],   // W_fc
        (const float*)d_in[10],  // b_fc
        (float*)d_out);
}